// round 12
// baseline (speedup 1.0000x reference)
#include <cuda_runtime.h>
#include <cuda_fp16.h>
#include <math.h>
#include <stdint.h>

#define N_NODES 20000
#define N_FEAT  2000
#define N_EDGES 640000
#define HID     128
#define OUTC    15
#define BN_EPS  1e-3f
#define KPAD    2048

// ---------------- scratch (device globals; no allocation allowed) ----------------
__device__ __half g_Ah[(size_t)N_NODES * KPAD];
__device__ __half g_Bh[(size_t)512 * KPAD];
__device__ __half g_Y [N_NODES * 512];   // fp16: x @ [W1_0|W1_1|W1_2|W1_3]
__device__ __half g_t0[N_NODES * HID];   // fp16 Horner temps
__device__ __half g_t1[N_NODES * HID];
__device__ float g_h [N_NODES * HID];    // fp32 post BN+ReLU (GEMM2 input)
__device__ float g_Z [N_NODES * 64];
__device__ float g_u0[N_NODES * 16];
__device__ float g_u1[N_NODES * 16];
__device__ int   g_counts[N_NODES];
__device__ int   g_rowptr[N_NODES + 1];
__device__ int   g_rowofs[N_NODES];
__device__ int   g_srcs[N_EDGES];
__device__ float g_ws [N_EDGES];

// ---------------- helpers ----------------
__device__ __forceinline__ uint32_t smem_u32(const void* p) {
    uint32_t a;
    asm("{ .reg .u64 t; cvta.to.shared.u64 t, %1; cvt.u32.u64 %0, t; }" : "=r"(a) : "l"(p));
    return a;
}
__device__ __forceinline__ void cp_async16(uint32_t dst, const void* src) {
    asm volatile("cp.async.cg.shared.global [%0], [%1], 16;" :: "r"(dst), "l"(src));
}
__device__ __forceinline__ void ldsm4(uint32_t* r, uint32_t addr) {
    asm volatile("ldmatrix.sync.aligned.m8n8.x4.shared.b16 {%0,%1,%2,%3}, [%4];"
                 : "=r"(r[0]), "=r"(r[1]), "=r"(r[2]), "=r"(r[3]) : "r"(addr));
}
// fp16-accumulator HMMA (rt=8): D(f16x4 in 2 regs) = A*B + C
__device__ __forceinline__ void mma16816hh(uint32_t* d, const uint32_t* a, const uint32_t* b) {
    asm volatile(
        "mma.sync.aligned.m16n8k16.row.col.f16.f16.f16.f16 "
        "{%0,%1}, {%2,%3,%4,%5}, {%6,%7}, {%0,%1};"
        : "+r"(d[0]), "+r"(d[1])
        : "r"(a[0]), "r"(a[1]), "r"(a[2]), "r"(a[3]), "r"(b[0]), "r"(b[1]));
}

// ---------------- CSR build ----------------
__global__ void k_zero() {
    int i = blockIdx.x * blockDim.x + threadIdx.x;
    if (i < N_NODES) { g_counts[i] = 0; g_rowofs[i] = 0; }
}
__global__ void k_hist(const int* __restrict__ dst) {
    int e = blockIdx.x * blockDim.x + threadIdx.x;
    if (e < N_EDGES) atomicAdd(&g_counts[dst[e]], 1);
}
__global__ void k_scan() {
    __shared__ int sh[1024];
    __shared__ int carry;
    if (threadIdx.x == 0) carry = 0;
    __syncthreads();
    for (int base = 0; base < N_NODES; base += 1024) {
        int i = base + threadIdx.x;
        int v = (i < N_NODES) ? g_counts[i] : 0;
        sh[threadIdx.x] = v;
        __syncthreads();
        for (int off = 1; off < 1024; off <<= 1) {
            int t = (threadIdx.x >= off) ? sh[threadIdx.x - off] : 0;
            __syncthreads();
            sh[threadIdx.x] += t;
            __syncthreads();
        }
        int incl = sh[threadIdx.x] + carry;
        if (i < N_NODES) g_rowptr[i + 1] = incl;
        __syncthreads();
        if (threadIdx.x == 1023) carry = incl;
        __syncthreads();
    }
    if (threadIdx.x == 0) g_rowptr[0] = 0;
}
__global__ void k_scatter(const int* __restrict__ src, const int* __restrict__ dst,
                          const float* __restrict__ w) {
    int e = blockIdx.x * blockDim.x + threadIdx.x;
    if (e < N_EDGES) {
        int d = dst[e];
        int pos = g_rowptr[d] + atomicAdd(&g_rowofs[d], 1);
        g_srcs[pos] = src[e];
        g_ws[pos]   = w[e];
    }
}

// ---------------- split conversions ----------------
// x -> fp16, 4 elements per thread (float4 -> half4)
__global__ void k_split_x(const float* __restrict__ x) {
    int idx = blockIdx.x * blockDim.x + threadIdx.x;
    if (idx >= N_NODES * 512) return;
    int r = idx >> 9, c4 = (idx & 511) * 4;
    uint2 o;
    if (c4 < N_FEAT) {
        float4 v = *(const float4*)&x[(size_t)r * N_FEAT + c4];
        *(__half2*)&o.x = __floats2half2_rn(v.x, v.y);
        *(__half2*)&o.y = __floats2half2_rn(v.z, v.w);
    } else {
        o.x = 0u; o.y = 0u;
    }
    *(uint2*)&g_Ah[(size_t)r * KPAD + c4] = o;
}
// Bh[n][k] = fp16(W1[(n>>7)*2000 + k, n&127]);  W1 is [8000,128] row-major
__global__ void k_split_w(const float* __restrict__ W1) {
    int idx = blockIdx.x * blockDim.x + threadIdx.x;
    if (idx >= 512 * KPAD) return;
    int n = idx >> 11, k = idx & (KPAD - 1);
    float v = (k < N_FEAT) ? W1[(size_t)((n >> 7) * N_FEAT + k) * HID + (n & 127)] : 0.f;
    g_Bh[idx] = __float2half_rn(v);
}

// ---------------- GEMM1 via mma.sync (HMMA fp16-acc, per-chunk fp32 promote) ----------------
// Y = fp16(x) @ fp16(W); fp16 accumulation inside each 64-K chunk (4 MMAs),
// promoted into fp32 master accumulators per chunk. fp16 output.
// CTA tile 192x128, 512 threads, 16 warps (4x4), warp tile 48x32, k-chunk 64.
// 3-stage cp.async ring, ONE __syncthreads per chunk. 144B rows => conflict-free ldmatrix.
#define RS      144                 // 128 data + 16 pad
#define ATILEB  (192 * RS)          // 27648
#define BTILEB  (128 * RS)          // 18432
#define STGB    (ATILEB + BTILEB)   // 46080
#define NCH     32                  // 2048 / 64
#define SMEM_G1 (3 * STGB)          // 138240
#define MTILE   192

__global__ __launch_bounds__(512, 1) void k_gemm1_mma() {
    extern __shared__ __align__(16) char smem[];
    uint32_t sb = smem_u32(smem);
    int tid = threadIdx.x;
    int lane = tid & 31, wid = tid >> 5;
    int warp_m = wid & 3, warp_n = wid >> 2;
    int n0   = blockIdx.x * 128;    // 0..3  N-tile (fast dim: share A tile in L2)
    int row0 = blockIdx.y * MTILE;  // 0..104

    float acc[3][4][4];             // fp32 master accumulators
#pragma unroll
    for (int mt = 0; mt < 3; mt++)
#pragma unroll
        for (int nt = 0; nt < 4; nt++)
#pragma unroll
            for (int i = 0; i < 4; i++) acc[mt][nt][i] = 0.f;

    // ldmatrix lane addressing
    int g = lane >> 3, r = lane & 7;
    uint32_t a_off = (uint32_t)((warp_m * 48 + (g & 1) * 8 + r) * RS + (g >> 1) * 16);
    uint32_t b_off = (uint32_t)((warp_n * 32 + (g >> 1) * 8 + r) * RS + (g & 1) * 16);

    // loads per chunk: A 192 rows x 8 segs + B 128 x 8 = 2560 cp16 => 5 per thread
    auto load_chunk = [&](int kc, int buf) {
        uint32_t ab = sb + buf * STGB;
        uint32_t bb = ab + ATILEB;
#pragma unroll
        for (int i = 0; i < 5; i++) {
            int idx = tid + i * 512;
            if (idx < 1536) {
                int rr = idx >> 3, seg = idx & 7;
                int grr = row0 + rr; if (grr >= N_NODES) grr = N_NODES - 1;
                cp_async16(ab + rr * RS + seg * 16,
                           g_Ah + (size_t)grr * KPAD + kc * 64 + seg * 8);
            } else {
                int j = idx - 1536;
                int rr = j >> 3, seg = j & 7;
                cp_async16(bb + rr * RS + seg * 16,
                           g_Bh + (size_t)(n0 + rr) * KPAD + kc * 64 + seg * 8);
            }
        }
        asm volatile("cp.async.commit_group;" ::: "memory");
    };

    load_chunk(0, 0);
    load_chunk(1, 1);

    int buf = 0;
    for (int c = 0; c < NCH; c++) {
        if (c + 1 < NCH) asm volatile("cp.async.wait_group 1;" ::: "memory");
        else             asm volatile("cp.async.wait_group 0;" ::: "memory");
        __syncthreads();
        uint32_t ab = sb + buf * STGB;
        uint32_t bb = ab + ATILEB;
        if (c + 2 < NCH) {
            int nbuf = buf + 2; if (nbuf >= 3) nbuf -= 3;
            load_chunk(c + 2, nbuf);
        }
        // fp16 chunk accumulators (zeroed per chunk)
        uint32_t hacc[3][4][2];
#pragma unroll
        for (int mt = 0; mt < 3; mt++)
#pragma unroll
            for (int nt = 0; nt < 4; nt++) { hacc[mt][nt][0] = 0u; hacc[mt][nt][1] = 0u; }
#pragma unroll
        for (int ks = 0; ks < 4; ks++) {
            uint32_t afr[3][4], bfr[2][4];
#pragma unroll
            for (int mt = 0; mt < 3; mt++)
                ldsm4(afr[mt], ab + a_off + mt * 16 * RS + ks * 32);
#pragma unroll
            for (int bp = 0; bp < 2; bp++)
                ldsm4(bfr[bp], bb + b_off + bp * 16 * RS + ks * 32);
#pragma unroll
            for (int mt = 0; mt < 3; mt++)
#pragma unroll
                for (int nt = 0; nt < 4; nt++)
                    mma16816hh(hacc[mt][nt], afr[mt], &bfr[nt >> 1][(nt & 1) * 2]);
        }
        // promote chunk partials into fp32 masters
#pragma unroll
        for (int mt = 0; mt < 3; mt++)
#pragma unroll
            for (int nt = 0; nt < 4; nt++) {
                float2 p0 = __half22float2(*(__half2*)&hacc[mt][nt][0]);
                float2 p1 = __half22float2(*(__half2*)&hacc[mt][nt][1]);
                acc[mt][nt][0] += p0.x; acc[mt][nt][1] += p0.y;
                acc[mt][nt][2] += p1.x; acc[mt][nt][3] += p1.y;
            }
        buf++; if (buf >= 3) buf -= 3;
    }

    // epilogue: fp16 output
    int erow = warp_m * 48 + (lane >> 2);
    int ecol = n0 + warp_n * 32 + (lane & 3) * 2;
#pragma unroll
    for (int mt = 0; mt < 3; mt++) {
#pragma unroll
        for (int nt = 0; nt < 4; nt++) {
            int rr = row0 + erow + mt * 16;
            int cc = ecol + nt * 8;
            if (rr < N_NODES)
                *(__half2*)&g_Y[(size_t)rr * 512 + cc] =
                    __floats2half2_rn(acc[mt][nt][0], acc[mt][nt][1]);
            if (rr + 8 < N_NODES)
                *(__half2*)&g_Y[(size_t)(rr + 8) * 512 + cc] =
                    __floats2half2_rn(acc[mt][nt][2], acc[mt][nt][3]);
        }
    }
}

// ---------------- 128-wide propagation on fp16 arrays (fp32 accumulate, MLP 8) ----------------
__device__ __forceinline__ void h4_to_f4(const __half* p, float* f) {
    uint2 u = *(const uint2*)p;
    __half2 h0 = *(__half2*)&u.x;
    __half2 h1 = *(__half2*)&u.y;
    float2 a = __half22float2(h0), b = __half22float2(h1);
    f[0] = a.x; f[1] = a.y; f[2] = b.x; f[3] = b.y;
}

__device__ __forceinline__ void prop128_body(const __half* __restrict__ in,
                                             int inStride, int inOfs,
                                             float* acc, int gw, int c) {
    int beg = g_rowptr[gw], end = g_rowptr[gw + 1];
    int j = beg;
    for (; j + 8 <= end; j += 8) {
        int   s[8];
        float w[8];
        float v[8][4];
#pragma unroll
        for (int q = 0; q < 8; q++) { s[q] = g_srcs[j + q]; w[q] = g_ws[j + q]; }
#pragma unroll
        for (int q = 0; q < 8; q++)
            h4_to_f4(in + (size_t)s[q] * inStride + inOfs + c, v[q]);
#pragma unroll
        for (int q = 0; q < 8; q++) {
            acc[0] += w[q] * v[q][0]; acc[1] += w[q] * v[q][1];
            acc[2] += w[q] * v[q][2]; acc[3] += w[q] * v[q][3];
        }
    }
    for (; j < end; j++) {
        int s = g_srcs[j];
        float w = g_ws[j];
        float v[4];
        h4_to_f4(in + (size_t)s * inStride + inOfs + c, v);
#pragma unroll
        for (int q = 0; q < 4; q++) acc[q] += w * v[q];
    }
}

__global__ void k_prop128(const __half* __restrict__ in, int inStride, int inOfs,
                          const __half* __restrict__ add, int addStride, int addOfs,
                          __half* __restrict__ out) {
    int gw = (blockIdx.x * blockDim.x + threadIdx.x) >> 5;
    int lane = threadIdx.x & 31;
    if (gw >= N_NODES) return;
    int c = lane * 4;
    float acc[4];
    h4_to_f4(add + (size_t)gw * addStride + addOfs + c, acc);
    prop128_body(in, inStride, inOfs, acc, gw, c);
    uint2 o;
    *(__half2*)&o.x = __floats2half2_rn(acc[0], acc[1]);
    *(__half2*)&o.y = __floats2half2_rn(acc[2], acc[3]);
    *(uint2*)&out[(size_t)gw * HID + c] = o;
}

__global__ void k_prop128_final(const __half* __restrict__ in, int inStride, int inOfs,
                                const __half* __restrict__ add, int addStride, int addOfs,
                                const float* __restrict__ b1, const float* __restrict__ gamma,
                                const float* __restrict__ beta, const float* __restrict__ mean,
                                const float* __restrict__ var) {
    int gw = (blockIdx.x * blockDim.x + threadIdx.x) >> 5;
    int lane = threadIdx.x & 31;
    if (gw >= N_NODES) return;
    int c = lane * 4;
    float acc[4];
    h4_to_f4(add + (size_t)gw * addStride + addOfs + c, acc);
    prop128_body(in, inStride, inOfs, acc, gw, c);
    float4 bb = *(const float4*)&b1[c];
    float4 gg = *(const float4*)&gamma[c];
    float4 be = *(const float4*)&beta[c];
    float4 mm = *(const float4*)&mean[c];
    float4 vv = *(const float4*)&var[c];
    float4 r;
    r.x = fmaxf((acc[0] + bb.x - mm.x) * rsqrtf(vv.x + BN_EPS) * gg.x + be.x, 0.f);
    r.y = fmaxf((acc[1] + bb.y - mm.y) * rsqrtf(vv.y + BN_EPS) * gg.y + be.y, 0.f);
    r.z = fmaxf((acc[2] + bb.z - mm.z) * rsqrtf(vv.z + BN_EPS) * gg.z + be.z, 0.f);
    r.w = fmaxf((acc[3] + bb.w - mm.w) * rsqrtf(vv.w + BN_EPS) * gg.w + be.w, 0.f);
    *(float4*)&g_h[(size_t)gw * HID + c] = r;
}

// ---------------- GEMM2 ----------------
__global__ __launch_bounds__(256) void k_gemm2(const float* __restrict__ W2) {
    __shared__ float Ws[128 * 60];
    int row0 = blockIdx.x * 64;
    int tid = threadIdx.x;
    for (int idx = tid; idx < 128 * 60; idx += 256) {
        int f = idx / 60, j = idx % 60;
        int k = j / 15, cc = j % 15;
        Ws[idx] = W2[(size_t)(k * HID + f) * OUTC + cc];
    }
    __syncthreads();
    int r = tid >> 2, cg = tid & 3;
    int n = row0 + r;
    float acc[15];
#pragma unroll
    for (int c = 0; c < 15; c++) acc[c] = 0.f;
    if (n < N_NODES) {
        const float* hp = g_h + (size_t)n * HID;
#pragma unroll 4
        for (int f = 0; f < 128; f++) {
            float a = __ldg(hp + f);
            const float* wrow = &Ws[f * 60 + cg * 15];
#pragma unroll
            for (int c = 0; c < 15; c++) acc[c] += a * wrow[c];
        }
        float* zp = g_Z + (size_t)n * 64 + cg * 16;
#pragma unroll
        for (int c = 0; c < 15; c++) zp[c] = acc[c];
        zp[15] = 0.f;
    }
}

// ---------------- 16-wide propagation (2 nodes per warp, unrolled x4) ----------------
__device__ __forceinline__ float prop16_body(const float* __restrict__ in,
                                             int inStride, int inOfs,
                                             float acc, int gw, int lane) {
    int beg = g_rowptr[gw], end = g_rowptr[gw + 1];
    int j = beg;
    for (; j + 4 <= end; j += 4) {
        int s0 = g_srcs[j], s1 = g_srcs[j + 1], s2 = g_srcs[j + 2], s3 = g_srcs[j + 3];
        float w0 = g_ws[j], w1 = g_ws[j + 1], w2 = g_ws[j + 2], w3 = g_ws[j + 3];
        float v0 = in[(size_t)s0 * inStride + inOfs + lane];
        float v1 = in[(size_t)s1 * inStride + inOfs + lane];
        float v2 = in[(size_t)s2 * inStride + inOfs + lane];
        float v3 = in[(size_t)s3 * inStride + inOfs + lane];
        acc += w0 * v0 + w1 * v1 + w2 * v2 + w3 * v3;
    }
    for (; j < end; j++)
        acc += g_ws[j] * in[(size_t)g_srcs[j] * inStride + inOfs + lane];
    return acc;
}

__global__ void k_prop16(const float* __restrict__ in, int inStride, int inOfs,
                         const float* __restrict__ add, int addStride, int addOfs,
                         float* __restrict__ out) {
    int gw = (blockIdx.x * blockDim.x + threadIdx.x) >> 5;
    int lane = threadIdx.x & 31;
    int node = gw * 2 + (lane >> 4);
    int l = lane & 15;
    if (node >= N_NODES) return;
    float acc = add[(size_t)node * addStride + addOfs + l];
    acc = prop16_body(in, inStride, inOfs, acc, node, l);
    out[(size_t)node * 16 + l] = acc;
}

__global__ void k_prop16_final(const float* __restrict__ in, int inStride, int inOfs,
                               const float* __restrict__ add, int addStride, int addOfs,
                               const float* __restrict__ b2, float* __restrict__ out15) {
    int gw = (blockIdx.x * blockDim.x + threadIdx.x) >> 5;
    int lane = threadIdx.x & 31;
    int node = gw * 2 + (lane >> 4);
    int l = lane & 15;
    if (node >= N_NODES || l >= 15) return;
    float acc = add[(size_t)node * addStride + addOfs + l];
    acc = prop16_body(in, inStride, inOfs, acc, node, l);
    out15[(size_t)node * OUTC + l] = acc + b2[l];
}

// ---------------- launch ----------------
extern "C" void kernel_launch(void* const* d_in, const int* in_sizes, int n_in,
                              void* d_out, int out_size) {
    const float* x     = (const float*)d_in[0];
    const int*   esrc  = (const int*)d_in[1];
    const int*   edst  = (const int*)d_in[2];
    const float* ew    = (const float*)d_in[3];
    const float* W1    = (const float*)d_in[4];
    const float* b1    = (const float*)d_in[5];
    const float* gamma = (const float*)d_in[6];
    const float* beta  = (const float*)d_in[7];
    const float* mmean = (const float*)d_in[8];
    const float* mvar  = (const float*)d_in[9];
    const float* W2    = (const float*)d_in[10];
    const float* b2    = (const float*)d_in[11];
    float* out = (float*)d_out;

    __half *pY, *pt0, *pt1;
    float *pZ, *pu0, *pu1;
    cudaGetSymbolAddress((void**)&pY,  g_Y);
    cudaGetSymbolAddress((void**)&pt0, g_t0);
    cudaGetSymbolAddress((void**)&pt1, g_t1);
    cudaGetSymbolAddress((void**)&pZ,  g_Z);
    cudaGetSymbolAddress((void**)&pu0, g_u0);
    cudaGetSymbolAddress((void**)&pu1, g_u1);

    cudaFuncSetAttribute(k_gemm1_mma, cudaFuncAttributeMaxDynamicSharedMemorySize, SMEM_G1);

    // Second stream: split_w (needed by gemm1, joined via evW) then the CSR
    // build (independent; joined via evJoin before props). Host-side API only.
    cudaStream_t s2;
    cudaEvent_t evFork, evW, evJoin;
    cudaStreamCreateWithFlags(&s2, cudaStreamNonBlocking);
    cudaEventCreateWithFlags(&evFork, cudaEventDisableTiming);
    cudaEventCreateWithFlags(&evW,    cudaEventDisableTiming);
    cudaEventCreateWithFlags(&evJoin, cudaEventDisableTiming);

    cudaEventRecord(evFork, 0);
    cudaStreamWaitEvent(s2, evFork, 0);
    k_split_w<<<(512 * KPAD + 255) / 256, 256, 0, s2>>>(W1);
    cudaEventRecord(evW, s2);
    k_zero<<<(N_NODES + 255) / 256, 256, 0, s2>>>();
    k_hist<<<(N_EDGES + 255) / 256, 256, 0, s2>>>(edst);
    k_scan<<<1, 1024, 0, s2>>>();
    k_scatter<<<(N_EDGES + 255) / 256, 256, 0, s2>>>(esrc, edst, ew);
    cudaEventRecord(evJoin, s2);

    // Main stream: split_x, then (after split_w) tensor-core GEMM1.
    k_split_x<<<(N_NODES * 512 + 255) / 256, 256>>>(x);
    cudaStreamWaitEvent(0, evW, 0);
    dim3 g1(4, (N_NODES + MTILE - 1) / MTILE);
    k_gemm1_mma<<<g1, 512, SMEM_G1>>>();

    // Join: props need both Y (main) and CSR (s2).
    cudaStreamWaitEvent(0, evJoin, 0);

    int pb = (N_NODES * 32 + 255) / 256;
    int pb2 = (N_NODES * 16 + 255) / 256;
    k_prop128<<<pb, 256>>>(pY, 512, 384, pY, 512, 256, pt0);   // t0 = y2 + A*y3
    k_prop128<<<pb, 256>>>(pt0, 128, 0,  pY, 512, 128, pt1);   // t1 = y1 + A*t0
    k_prop128_final<<<pb, 256>>>(pt1, 128, 0, pY, 512, 0,      // h = BNReLU(y0 + A*t1 + b1)
                                 b1, gamma, beta, mmean, mvar);

    k_gemm2<<<(N_NODES + 63) / 64, 256>>>(W2);
    k_prop16<<<pb2, 256>>>(pZ, 64, 48, pZ, 64, 32, pu0);
    k_prop16<<<pb2, 256>>>(pu0, 16, 0, pZ, 64, 16, pu1);
    k_prop16_final<<<pb2, 256>>>(pu1, 16, 0, pZ, 64, 0, b2, out);
}

// round 13
// speedup vs baseline: 1.0015x; 1.0015x over previous
#include <cuda_runtime.h>
#include <cuda_fp16.h>
#include <math.h>
#include <stdint.h>

#define N_NODES 20000
#define N_FEAT  2000
#define N_EDGES 640000
#define HID     128
#define OUTC    15
#define BN_EPS  1e-3f
#define KPAD    2048

// ---------------- scratch (device globals; no allocation allowed) ----------------
__device__ __half g_Ah[(size_t)N_NODES * KPAD];
__device__ __half g_Bh[(size_t)512 * KPAD];
__device__ __half g_Y [N_NODES * 512];   // fp16: x @ [W1_0|W1_1|W1_2|W1_3]
__device__ __half g_t0[N_NODES * HID];   // fp16 Horner temps
__device__ __half g_t1[N_NODES * HID];
__device__ float g_h [N_NODES * HID];    // fp32 post BN+ReLU (GEMM2 input)
__device__ float g_Z [N_NODES * 64];
__device__ float g_u0[N_NODES * 16];
__device__ float g_u1[N_NODES * 16];
__device__ int   g_counts[N_NODES];
__device__ int   g_rowptr[N_NODES + 1];
__device__ int   g_rowofs[N_NODES];
__device__ int   g_srcs[N_EDGES];
__device__ float g_ws [N_EDGES];

// ---------------- helpers ----------------
__device__ __forceinline__ uint32_t smem_u32(const void* p) {
    uint32_t a;
    asm("{ .reg .u64 t; cvta.to.shared.u64 t, %1; cvt.u32.u64 %0, t; }" : "=r"(a) : "l"(p));
    return a;
}
__device__ __forceinline__ void cp_async16(uint32_t dst, const void* src) {
    asm volatile("cp.async.cg.shared.global [%0], [%1], 16;" :: "r"(dst), "l"(src));
}
__device__ __forceinline__ void ldsm4(uint32_t* r, uint32_t addr) {
    asm volatile("ldmatrix.sync.aligned.m8n8.x4.shared.b16 {%0,%1,%2,%3}, [%4];"
                 : "=r"(r[0]), "=r"(r[1]), "=r"(r[2]), "=r"(r[3]) : "r"(addr));
}
__device__ __forceinline__ void mma16816h(float* d, const uint32_t* a, const uint32_t* b) {
    asm volatile(
        "mma.sync.aligned.m16n8k16.row.col.f32.f16.f16.f32 "
        "{%0,%1,%2,%3}, {%4,%5,%6,%7}, {%8,%9}, {%0,%1,%2,%3};"
        : "+f"(d[0]), "+f"(d[1]), "+f"(d[2]), "+f"(d[3])
        : "r"(a[0]), "r"(a[1]), "r"(a[2]), "r"(a[3]), "r"(b[0]), "r"(b[1]));
}

// ---------------- CSR build ----------------
__global__ void k_zero() {
    int i = blockIdx.x * blockDim.x + threadIdx.x;
    if (i < N_NODES) { g_counts[i] = 0; g_rowofs[i] = 0; }
}
__global__ void k_hist(const int* __restrict__ dst) {
    int e = blockIdx.x * blockDim.x + threadIdx.x;
    if (e < N_EDGES) atomicAdd(&g_counts[dst[e]], 1);
}
__global__ void k_scan() {
    __shared__ int sh[1024];
    __shared__ int carry;
    if (threadIdx.x == 0) carry = 0;
    __syncthreads();
    for (int base = 0; base < N_NODES; base += 1024) {
        int i = base + threadIdx.x;
        int v = (i < N_NODES) ? g_counts[i] : 0;
        sh[threadIdx.x] = v;
        __syncthreads();
        for (int off = 1; off < 1024; off <<= 1) {
            int t = (threadIdx.x >= off) ? sh[threadIdx.x - off] : 0;
            __syncthreads();
            sh[threadIdx.x] += t;
            __syncthreads();
        }
        int incl = sh[threadIdx.x] + carry;
        if (i < N_NODES) g_rowptr[i + 1] = incl;
        __syncthreads();
        if (threadIdx.x == 1023) carry = incl;
        __syncthreads();
    }
    if (threadIdx.x == 0) g_rowptr[0] = 0;
}
__global__ void k_scatter(const int* __restrict__ src, const int* __restrict__ dst,
                          const float* __restrict__ w) {
    int e = blockIdx.x * blockDim.x + threadIdx.x;
    if (e < N_EDGES) {
        int d = dst[e];
        int pos = g_rowptr[d] + atomicAdd(&g_rowofs[d], 1);
        g_srcs[pos] = src[e];
        g_ws[pos]   = w[e];
    }
}

// ---------------- split conversions ----------------
// x -> fp16, 4 elements per thread (float4 -> half4)
__global__ void k_split_x(const float* __restrict__ x) {
    int idx = blockIdx.x * blockDim.x + threadIdx.x;
    if (idx >= N_NODES * 512) return;
    int r = idx >> 9, c4 = (idx & 511) * 4;
    uint2 o;
    if (c4 < N_FEAT) {
        float4 v = *(const float4*)&x[(size_t)r * N_FEAT + c4];
        *(__half2*)&o.x = __floats2half2_rn(v.x, v.y);
        *(__half2*)&o.y = __floats2half2_rn(v.z, v.w);
    } else {
        o.x = 0u; o.y = 0u;
    }
    *(uint2*)&g_Ah[(size_t)r * KPAD + c4] = o;
}
// Bh[n][k] = fp16(W1[(n>>7)*2000 + k, n&127]);  W1 is [8000,128] row-major
__global__ void k_split_w(const float* __restrict__ W1) {
    int idx = blockIdx.x * blockDim.x + threadIdx.x;
    if (idx >= 512 * KPAD) return;
    int n = idx >> 11, k = idx & (KPAD - 1);
    float v = (k < N_FEAT) ? W1[(size_t)((n >> 7) * N_FEAT + k) * HID + (n & 127)] : 0.f;
    g_Bh[idx] = __float2half_rn(v);
}

// ---------------- GEMM1 via mma.sync (HMMA fp16, fp32 accum — proven config) ----------------
// Y = fp16(x) @ fp16(W), fp32 accum, fp16 output.
// CTA tile 192x128, 512 threads, 16 warps (4x4), warp tile 48x32, k-chunk 64.
// 3-stage cp.async ring, ONE __syncthreads per chunk. 144B rows => conflict-free ldmatrix.
#define RS      144                 // 128 data + 16 pad
#define ATILEB  (192 * RS)          // 27648
#define BTILEB  (128 * RS)          // 18432
#define STGB    (ATILEB + BTILEB)   // 46080
#define NCH     32                  // 2048 / 64
#define SMEM_G1 (3 * STGB)          // 138240
#define MTILE   192

__global__ __launch_bounds__(512, 1) void k_gemm1_mma() {
    extern __shared__ __align__(16) char smem[];
    uint32_t sb = smem_u32(smem);
    int tid = threadIdx.x;
    int lane = tid & 31, wid = tid >> 5;
    int warp_m = wid & 3, warp_n = wid >> 2;
    int n0   = blockIdx.x * 128;    // 0..3  N-tile (fast dim: share A tile in L2)
    int row0 = blockIdx.y * MTILE;  // 0..104

    float acc[3][4][4];
#pragma unroll
    for (int mt = 0; mt < 3; mt++)
#pragma unroll
        for (int nt = 0; nt < 4; nt++)
#pragma unroll
            for (int i = 0; i < 4; i++) acc[mt][nt][i] = 0.f;

    // ldmatrix lane addressing
    int g = lane >> 3, r = lane & 7;
    uint32_t a_off = (uint32_t)((warp_m * 48 + (g & 1) * 8 + r) * RS + (g >> 1) * 16);
    uint32_t b_off = (uint32_t)((warp_n * 32 + (g >> 1) * 8 + r) * RS + (g & 1) * 16);

    // loads per chunk: A 192 rows x 8 segs + B 128 x 8 = 2560 cp16 => 5 per thread
    auto load_chunk = [&](int kc, int buf) {
        uint32_t ab = sb + buf * STGB;
        uint32_t bb = ab + ATILEB;
#pragma unroll
        for (int i = 0; i < 5; i++) {
            int idx = tid + i * 512;
            if (idx < 1536) {
                int rr = idx >> 3, seg = idx & 7;
                int grr = row0 + rr; if (grr >= N_NODES) grr = N_NODES - 1;
                cp_async16(ab + rr * RS + seg * 16,
                           g_Ah + (size_t)grr * KPAD + kc * 64 + seg * 8);
            } else {
                int j = idx - 1536;
                int rr = j >> 3, seg = j & 7;
                cp_async16(bb + rr * RS + seg * 16,
                           g_Bh + (size_t)(n0 + rr) * KPAD + kc * 64 + seg * 8);
            }
        }
        asm volatile("cp.async.commit_group;" ::: "memory");
    };

    load_chunk(0, 0);
    load_chunk(1, 1);

    int buf = 0;
    for (int c = 0; c < NCH; c++) {
        if (c + 1 < NCH) asm volatile("cp.async.wait_group 1;" ::: "memory");
        else             asm volatile("cp.async.wait_group 0;" ::: "memory");
        __syncthreads();
        uint32_t ab = sb + buf * STGB;
        uint32_t bb = ab + ATILEB;
        if (c + 2 < NCH) {
            int nbuf = buf + 2; if (nbuf >= 3) nbuf -= 3;
            load_chunk(c + 2, nbuf);
        }
#pragma unroll
        for (int ks = 0; ks < 4; ks++) {
            uint32_t afr[3][4], bfr[2][4];
#pragma unroll
            for (int mt = 0; mt < 3; mt++)
                ldsm4(afr[mt], ab + a_off + mt * 16 * RS + ks * 32);
#pragma unroll
            for (int bp = 0; bp < 2; bp++)
                ldsm4(bfr[bp], bb + b_off + bp * 16 * RS + ks * 32);
#pragma unroll
            for (int mt = 0; mt < 3; mt++)
#pragma unroll
                for (int nt = 0; nt < 4; nt++)
                    mma16816h(acc[mt][nt], afr[mt], &bfr[nt >> 1][(nt & 1) * 2]);
        }
        buf++; if (buf >= 3) buf -= 3;
    }

    // epilogue: fp16 output
    int erow = warp_m * 48 + (lane >> 2);
    int ecol = n0 + warp_n * 32 + (lane & 3) * 2;
#pragma unroll
    for (int mt = 0; mt < 3; mt++) {
#pragma unroll
        for (int nt = 0; nt < 4; nt++) {
            int rr = row0 + erow + mt * 16;
            int cc = ecol + nt * 8;
            if (rr < N_NODES)
                *(__half2*)&g_Y[(size_t)rr * 512 + cc] =
                    __floats2half2_rn(acc[mt][nt][0], acc[mt][nt][1]);
            if (rr + 8 < N_NODES)
                *(__half2*)&g_Y[(size_t)(rr + 8) * 512 + cc] =
                    __floats2half2_rn(acc[mt][nt][2], acc[mt][nt][3]);
        }
    }
}

// ---------------- 128-wide propagation on fp16 arrays (fp32 accumulate, MLP 8) ----------------
__device__ __forceinline__ void h4_to_f4(const __half* p, float* f) {
    uint2 u = *(const uint2*)p;
    __half2 h0 = *(__half2*)&u.x;
    __half2 h1 = *(__half2*)&u.y;
    float2 a = __half22float2(h0), b = __half22float2(h1);
    f[0] = a.x; f[1] = a.y; f[2] = b.x; f[3] = b.y;
}

__device__ __forceinline__ void prop128_body(const __half* __restrict__ in,
                                             int inStride, int inOfs,
                                             float* acc, int gw, int c) {
    int beg = g_rowptr[gw], end = g_rowptr[gw + 1];
    int j = beg;
    for (; j + 8 <= end; j += 8) {
        int   s[8];
        float w[8];
        float v[8][4];
#pragma unroll
        for (int q = 0; q < 8; q++) { s[q] = g_srcs[j + q]; w[q] = g_ws[j + q]; }
#pragma unroll
        for (int q = 0; q < 8; q++)
            h4_to_f4(in + (size_t)s[q] * inStride + inOfs + c, v[q]);
#pragma unroll
        for (int q = 0; q < 8; q++) {
            acc[0] += w[q] * v[q][0]; acc[1] += w[q] * v[q][1];
            acc[2] += w[q] * v[q][2]; acc[3] += w[q] * v[q][3];
        }
    }
    for (; j < end; j++) {
        int s = g_srcs[j];
        float w = g_ws[j];
        float v[4];
        h4_to_f4(in + (size_t)s * inStride + inOfs + c, v);
#pragma unroll
        for (int q = 0; q < 4; q++) acc[q] += w * v[q];
    }
}

__global__ void k_prop128(const __half* __restrict__ in, int inStride, int inOfs,
                          const __half* __restrict__ add, int addStride, int addOfs,
                          __half* __restrict__ out) {
    int gw = (blockIdx.x * blockDim.x + threadIdx.x) >> 5;
    int lane = threadIdx.x & 31;
    if (gw >= N_NODES) return;
    int c = lane * 4;
    float acc[4];
    h4_to_f4(add + (size_t)gw * addStride + addOfs + c, acc);
    prop128_body(in, inStride, inOfs, acc, gw, c);
    uint2 o;
    *(__half2*)&o.x = __floats2half2_rn(acc[0], acc[1]);
    *(__half2*)&o.y = __floats2half2_rn(acc[2], acc[3]);
    *(uint2*)&out[(size_t)gw * HID + c] = o;
}

__global__ void k_prop128_final(const __half* __restrict__ in, int inStride, int inOfs,
                                const __half* __restrict__ add, int addStride, int addOfs,
                                const float* __restrict__ b1, const float* __restrict__ gamma,
                                const float* __restrict__ beta, const float* __restrict__ mean,
                                const float* __restrict__ var) {
    int gw = (blockIdx.x * blockDim.x + threadIdx.x) >> 5;
    int lane = threadIdx.x & 31;
    if (gw >= N_NODES) return;
    int c = lane * 4;
    float acc[4];
    h4_to_f4(add + (size_t)gw * addStride + addOfs + c, acc);
    prop128_body(in, inStride, inOfs, acc, gw, c);
    float4 bb = *(const float4*)&b1[c];
    float4 gg = *(const float4*)&gamma[c];
    float4 be = *(const float4*)&beta[c];
    float4 mm = *(const float4*)&mean[c];
    float4 vv = *(const float4*)&var[c];
    float4 r;
    r.x = fmaxf((acc[0] + bb.x - mm.x) * rsqrtf(vv.x + BN_EPS) * gg.x + be.x, 0.f);
    r.y = fmaxf((acc[1] + bb.y - mm.y) * rsqrtf(vv.y + BN_EPS) * gg.y + be.y, 0.f);
    r.z = fmaxf((acc[2] + bb.z - mm.z) * rsqrtf(vv.z + BN_EPS) * gg.z + be.z, 0.f);
    r.w = fmaxf((acc[3] + bb.w - mm.w) * rsqrtf(vv.w + BN_EPS) * gg.w + be.w, 0.f);
    *(float4*)&g_h[(size_t)gw * HID + c] = r;
}

// ---------------- GEMM2 (Ws rows padded to 16 floats; LDS.128 reads) ----------------
__global__ __launch_bounds__(256) void k_gemm2(const float* __restrict__ W2) {
    __shared__ float Ws[128 * 64];   // [f][cg*16 + c], c<15 valid, c=15 pad
    int row0 = blockIdx.x * 64;
    int tid = threadIdx.x;
    for (int idx = tid; idx < 128 * 64; idx += 256) {
        int f = idx >> 6, j = idx & 63;
        int k = j >> 4, cc = j & 15;
        Ws[idx] = (cc < OUTC) ? W2[(size_t)(k * HID + f) * OUTC + cc] : 0.f;
    }
    __syncthreads();
    int r = tid >> 2, cg = tid & 3;
    int n = row0 + r;
    float acc[16];
#pragma unroll
    for (int c = 0; c < 16; c++) acc[c] = 0.f;
    if (n < N_NODES) {
        const float* hp = g_h + (size_t)n * HID;
#pragma unroll 4
        for (int f = 0; f < 128; f++) {
            float a = __ldg(hp + f);
            const float4* wrow = (const float4*)&Ws[f * 64 + cg * 16];
#pragma unroll
            for (int q = 0; q < 4; q++) {
                float4 wv = wrow[q];
                acc[q * 4 + 0] += a * wv.x;
                acc[q * 4 + 1] += a * wv.y;
                acc[q * 4 + 2] += a * wv.z;
                acc[q * 4 + 3] += a * wv.w;
            }
        }
        float* zp = g_Z + (size_t)n * 64 + cg * 16;
#pragma unroll
        for (int q = 0; q < 4; q++)
            *(float4*)(zp + q * 4) = make_float4(acc[q * 4], acc[q * 4 + 1],
                                                 acc[q * 4 + 2], acc[q * 4 + 3]);
    }
}

// ---------------- 16-wide propagation (2 nodes per warp, unrolled x8) ----------------
__device__ __forceinline__ float prop16_body(const float* __restrict__ in,
                                             int inStride, int inOfs,
                                             float acc, int gw, int lane) {
    int beg = g_rowptr[gw], end = g_rowptr[gw + 1];
    int j = beg;
    for (; j + 8 <= end; j += 8) {
        int   s[8];
        float w[8], v[8];
#pragma unroll
        for (int q = 0; q < 8; q++) { s[q] = g_srcs[j + q]; w[q] = g_ws[j + q]; }
#pragma unroll
        for (int q = 0; q < 8; q++)
            v[q] = in[(size_t)s[q] * inStride + inOfs + lane];
#pragma unroll
        for (int q = 0; q < 8; q++) acc += w[q] * v[q];
    }
    for (; j < end; j++)
        acc += g_ws[j] * in[(size_t)g_srcs[j] * inStride + inOfs + lane];
    return acc;
}

__global__ void k_prop16(const float* __restrict__ in, int inStride, int inOfs,
                         const float* __restrict__ add, int addStride, int addOfs,
                         float* __restrict__ out) {
    int gw = (blockIdx.x * blockDim.x + threadIdx.x) >> 5;
    int lane = threadIdx.x & 31;
    int node = gw * 2 + (lane >> 4);
    int l = lane & 15;
    if (node >= N_NODES) return;
    float acc = add[(size_t)node * addStride + addOfs + l];
    acc = prop16_body(in, inStride, inOfs, acc, node, l);
    out[(size_t)node * 16 + l] = acc;
}

__global__ void k_prop16_final(const float* __restrict__ in, int inStride, int inOfs,
                               const float* __restrict__ add, int addStride, int addOfs,
                               const float* __restrict__ b2, float* __restrict__ out15) {
    int gw = (blockIdx.x * blockDim.x + threadIdx.x) >> 5;
    int lane = threadIdx.x & 31;
    int node = gw * 2 + (lane >> 4);
    int l = lane & 15;
    if (node >= N_NODES || l >= 15) return;
    float acc = add[(size_t)node * addStride + addOfs + l];
    acc = prop16_body(in, inStride, inOfs, acc, node, l);
    out15[(size_t)node * OUTC + l] = acc + b2[l];
}

// ---------------- launch ----------------
extern "C" void kernel_launch(void* const* d_in, const int* in_sizes, int n_in,
                              void* d_out, int out_size) {
    const float* x     = (const float*)d_in[0];
    const int*   esrc  = (const int*)d_in[1];
    const int*   edst  = (const int*)d_in[2];
    const float* ew    = (const float*)d_in[3];
    const float* W1    = (const float*)d_in[4];
    const float* b1    = (const float*)d_in[5];
    const float* gamma = (const float*)d_in[6];
    const float* beta  = (const float*)d_in[7];
    const float* mmean = (const float*)d_in[8];
    const float* mvar  = (const float*)d_in[9];
    const float* W2    = (const float*)d_in[10];
    const float* b2    = (const float*)d_in[11];
    float* out = (float*)d_out;

    __half *pY, *pt0, *pt1;
    float *pZ, *pu0, *pu1;
    cudaGetSymbolAddress((void**)&pY,  g_Y);
    cudaGetSymbolAddress((void**)&pt0, g_t0);
    cudaGetSymbolAddress((void**)&pt1, g_t1);
    cudaGetSymbolAddress((void**)&pZ,  g_Z);
    cudaGetSymbolAddress((void**)&pu0, g_u0);
    cudaGetSymbolAddress((void**)&pu1, g_u1);

    cudaFuncSetAttribute(k_gemm1_mma, cudaFuncAttributeMaxDynamicSharedMemorySize, SMEM_G1);

    // Second stream: split_w (needed by gemm1, joined via evW) then the CSR
    // build (independent; joined via evJoin before props). Host-side API only.
    cudaStream_t s2;
    cudaEvent_t evFork, evW, evJoin;
    cudaStreamCreateWithFlags(&s2, cudaStreamNonBlocking);
    cudaEventCreateWithFlags(&evFork, cudaEventDisableTiming);
    cudaEventCreateWithFlags(&evW,    cudaEventDisableTiming);
    cudaEventCreateWithFlags(&evJoin, cudaEventDisableTiming);

    cudaEventRecord(evFork, 0);
    cudaStreamWaitEvent(s2, evFork, 0);
    k_split_w<<<(512 * KPAD + 255) / 256, 256, 0, s2>>>(W1);
    cudaEventRecord(evW, s2);
    k_zero<<<(N_NODES + 255) / 256, 256, 0, s2>>>();
    k_hist<<<(N_EDGES + 255) / 256, 256, 0, s2>>>(edst);
    k_scan<<<1, 1024, 0, s2>>>();
    k_scatter<<<(N_EDGES + 255) / 256, 256, 0, s2>>>(esrc, edst, ew);
    cudaEventRecord(evJoin, s2);

    // Main stream: split_x, then (after split_w) tensor-core GEMM1.
    k_split_x<<<(N_NODES * 512 + 255) / 256, 256>>>(x);
    cudaStreamWaitEvent(0, evW, 0);
    dim3 g1(4, (N_NODES + MTILE - 1) / MTILE);
    k_gemm1_mma<<<g1, 512, SMEM_G1>>>();

    // Join: props need both Y (main) and CSR (s2).
    cudaStreamWaitEvent(0, evJoin, 0);

    int pb = (N_NODES * 32 + 255) / 256;
    int pb2 = (N_NODES * 16 + 255) / 256;
    k_prop128<<<pb, 256>>>(pY, 512, 384, pY, 512, 256, pt0);   // t0 = y2 + A*y3
    k_prop128<<<pb, 256>>>(pt0, 128, 0,  pY, 512, 128, pt1);   // t1 = y1 + A*t0
    k_prop128_final<<<pb, 256>>>(pt1, 128, 0, pY, 512, 0,      // h = BNReLU(y0 + A*t1 + b1)
                                 b1, gamma, beta, mmean, mvar);

    k_gemm2<<<(N_NODES + 63) / 64, 256>>>(W2);
    k_prop16<<<pb2, 256>>>(pZ, 64, 48, pZ, 64, 32, pu0);
    k_prop16<<<pb2, 256>>>(pu0, 16, 0, pZ, 64, 16, pu1);
    k_prop16_final<<<pb2, 256>>>(pu1, 16, 0, pZ, 64, 0, b2, out);
}

// round 14
// speedup vs baseline: 1.0271x; 1.0255x over previous
#include <cuda_runtime.h>
#include <cuda_fp16.h>
#include <math.h>
#include <stdint.h>

#define N_NODES 20000
#define N_FEAT  2000
#define N_EDGES 640000
#define HID     128
#define OUTC    15
#define BN_EPS  1e-3f
#define KPAD    2048

// ---------------- scratch (device globals; no allocation allowed) ----------------
__device__ __half g_Ah[(size_t)N_NODES * KPAD];
__device__ __half g_Bh[(size_t)512 * KPAD];
__device__ __half g_Y [N_NODES * 512];   // fp16: x @ [W1_0|W1_1|W1_2|W1_3]
__device__ __half g_t0[N_NODES * HID];   // fp16 Horner temps
__device__ __half g_t1[N_NODES * HID];
__device__ float g_h [N_NODES * HID];    // fp32 post BN+ReLU (GEMM2 input)
__device__ float g_Z [N_NODES * 64];
__device__ float g_u0[N_NODES * 16];
__device__ float g_u1[N_NODES * 16];
__device__ int   g_counts[N_NODES];
__device__ int   g_rowptr[N_NODES + 1];
__device__ int   g_rowofs[N_NODES];
__device__ int   g_srcs[N_EDGES];
__device__ float g_ws [N_EDGES];

// ---------------- helpers ----------------
__device__ __forceinline__ uint32_t smem_u32(const void* p) {
    uint32_t a;
    asm("{ .reg .u64 t; cvta.to.shared.u64 t, %1; cvt.u32.u64 %0, t; }" : "=r"(a) : "l"(p));
    return a;
}
__device__ __forceinline__ void cp_async16(uint32_t dst, const void* src) {
    asm volatile("cp.async.cg.shared.global [%0], [%1], 16;" :: "r"(dst), "l"(src));
}
__device__ __forceinline__ void ldsm4(uint32_t* r, uint32_t addr) {
    asm volatile("ldmatrix.sync.aligned.m8n8.x4.shared.b16 {%0,%1,%2,%3}, [%4];"
                 : "=r"(r[0]), "=r"(r[1]), "=r"(r[2]), "=r"(r[3]) : "r"(addr));
}
__device__ __forceinline__ void mma16816h(float* d, const uint32_t* a, const uint32_t* b) {
    asm volatile(
        "mma.sync.aligned.m16n8k16.row.col.f32.f16.f16.f32 "
        "{%0,%1,%2,%3}, {%4,%5,%6,%7}, {%8,%9}, {%0,%1,%2,%3};"
        : "+f"(d[0]), "+f"(d[1]), "+f"(d[2]), "+f"(d[3])
        : "r"(a[0]), "r"(a[1]), "r"(a[2]), "r"(a[3]), "r"(b[0]), "r"(b[1]));
}

// ---------------- CSR build ----------------
__global__ void k_zero() {
    int i = blockIdx.x * blockDim.x + threadIdx.x;
    if (i < N_NODES) { g_counts[i] = 0; g_rowofs[i] = 0; }
}
__global__ void k_hist(const int* __restrict__ dst) {
    int e = blockIdx.x * blockDim.x + threadIdx.x;
    if (e < N_EDGES) atomicAdd(&g_counts[dst[e]], 1);
}
__global__ void k_scan() {
    __shared__ int sh[1024];
    __shared__ int carry;
    if (threadIdx.x == 0) carry = 0;
    __syncthreads();
    for (int base = 0; base < N_NODES; base += 1024) {
        int i = base + threadIdx.x;
        int v = (i < N_NODES) ? g_counts[i] : 0;
        sh[threadIdx.x] = v;
        __syncthreads();
        for (int off = 1; off < 1024; off <<= 1) {
            int t = (threadIdx.x >= off) ? sh[threadIdx.x - off] : 0;
            __syncthreads();
            sh[threadIdx.x] += t;
            __syncthreads();
        }
        int incl = sh[threadIdx.x] + carry;
        if (i < N_NODES) g_rowptr[i + 1] = incl;
        __syncthreads();
        if (threadIdx.x == 1023) carry = incl;
        __syncthreads();
    }
    if (threadIdx.x == 0) g_rowptr[0] = 0;
}
__global__ void k_scatter(const int* __restrict__ src, const int* __restrict__ dst,
                          const float* __restrict__ w) {
    int e = blockIdx.x * blockDim.x + threadIdx.x;
    if (e < N_EDGES) {
        int d = dst[e];
        int pos = g_rowptr[d] + atomicAdd(&g_rowofs[d], 1);
        g_srcs[pos] = src[e];
        g_ws[pos]   = w[e];
    }
}

// ---------------- split conversions ----------------
// x -> fp16, 4 elements per thread (float4 -> half4)
__global__ void k_split_x(const float* __restrict__ x) {
    int idx = blockIdx.x * blockDim.x + threadIdx.x;
    if (idx >= N_NODES * 512) return;
    int r = idx >> 9, c4 = (idx & 511) * 4;
    uint2 o;
    if (c4 < N_FEAT) {
        float4 v = *(const float4*)&x[(size_t)r * N_FEAT + c4];
        *(__half2*)&o.x = __floats2half2_rn(v.x, v.y);
        *(__half2*)&o.y = __floats2half2_rn(v.z, v.w);
    } else {
        o.x = 0u; o.y = 0u;
    }
    *(uint2*)&g_Ah[(size_t)r * KPAD + c4] = o;
}
// Bh[n][k] = fp16(W1[(n>>7)*2000 + k, n&127]);  W1 is [8000,128] row-major
__global__ void k_split_w(const float* __restrict__ W1) {
    int idx = blockIdx.x * blockDim.x + threadIdx.x;
    if (idx >= 512 * KPAD) return;
    int n = idx >> 11, k = idx & (KPAD - 1);
    float v = (k < N_FEAT) ? W1[(size_t)((n >> 7) * N_FEAT + k) * HID + (n & 127)] : 0.f;
    g_Bh[idx] = __float2half_rn(v);
}

// ---------------- GEMM1 via mma.sync (HMMA fp16, fp32 accum — proven config) ----------------
// Y = fp16(x) @ fp16(W), fp32 accum, fp16 output.
// CTA tile 192x128, 512 threads, 16 warps (4x4), warp tile 48x32, k-chunk 64.
// 3-stage cp.async ring, ONE __syncthreads per chunk. 144B rows => conflict-free ldmatrix.
#define RS      144                 // 128 data + 16 pad
#define ATILEB  (192 * RS)          // 27648
#define BTILEB  (128 * RS)          // 18432
#define STGB    (ATILEB + BTILEB)   // 46080
#define NCH     32                  // 2048 / 64
#define SMEM_G1 (3 * STGB)          // 138240
#define MTILE   192

__global__ __launch_bounds__(512, 1) void k_gemm1_mma() {
    extern __shared__ __align__(16) char smem[];
    uint32_t sb = smem_u32(smem);
    int tid = threadIdx.x;
    int lane = tid & 31, wid = tid >> 5;
    int warp_m = wid & 3, warp_n = wid >> 2;
    int n0   = blockIdx.x * 128;    // 0..3  N-tile (fast dim: share A tile in L2)
    int row0 = blockIdx.y * MTILE;  // 0..104

    float acc[3][4][4];
#pragma unroll
    for (int mt = 0; mt < 3; mt++)
#pragma unroll
        for (int nt = 0; nt < 4; nt++)
#pragma unroll
            for (int i = 0; i < 4; i++) acc[mt][nt][i] = 0.f;

    // ldmatrix lane addressing
    int g = lane >> 3, r = lane & 7;
    uint32_t a_off = (uint32_t)((warp_m * 48 + (g & 1) * 8 + r) * RS + (g >> 1) * 16);
    uint32_t b_off = (uint32_t)((warp_n * 32 + (g >> 1) * 8 + r) * RS + (g & 1) * 16);

    // loads per chunk: A 192 rows x 8 segs + B 128 x 8 = 2560 cp16 => 5 per thread
    auto load_chunk = [&](int kc, int buf) {
        uint32_t ab = sb + buf * STGB;
        uint32_t bb = ab + ATILEB;
#pragma unroll
        for (int i = 0; i < 5; i++) {
            int idx = tid + i * 512;
            if (idx < 1536) {
                int rr = idx >> 3, seg = idx & 7;
                int grr = row0 + rr; if (grr >= N_NODES) grr = N_NODES - 1;
                cp_async16(ab + rr * RS + seg * 16,
                           g_Ah + (size_t)grr * KPAD + kc * 64 + seg * 8);
            } else {
                int j = idx - 1536;
                int rr = j >> 3, seg = j & 7;
                cp_async16(bb + rr * RS + seg * 16,
                           g_Bh + (size_t)(n0 + rr) * KPAD + kc * 64 + seg * 8);
            }
        }
        asm volatile("cp.async.commit_group;" ::: "memory");
    };

    load_chunk(0, 0);
    load_chunk(1, 1);

    int buf = 0;
    for (int c = 0; c < NCH; c++) {
        if (c + 1 < NCH) asm volatile("cp.async.wait_group 1;" ::: "memory");
        else             asm volatile("cp.async.wait_group 0;" ::: "memory");
        __syncthreads();
        uint32_t ab = sb + buf * STGB;
        uint32_t bb = ab + ATILEB;
        if (c + 2 < NCH) {
            int nbuf = buf + 2; if (nbuf >= 3) nbuf -= 3;
            load_chunk(c + 2, nbuf);
        }
#pragma unroll
        for (int ks = 0; ks < 4; ks++) {
            uint32_t afr[3][4], bfr[2][4];
#pragma unroll
            for (int mt = 0; mt < 3; mt++)
                ldsm4(afr[mt], ab + a_off + mt * 16 * RS + ks * 32);
#pragma unroll
            for (int bp = 0; bp < 2; bp++)
                ldsm4(bfr[bp], bb + b_off + bp * 16 * RS + ks * 32);
#pragma unroll
            for (int mt = 0; mt < 3; mt++)
#pragma unroll
                for (int nt = 0; nt < 4; nt++)
                    mma16816h(acc[mt][nt], afr[mt], &bfr[nt >> 1][(nt & 1) * 2]);
        }
        buf++; if (buf >= 3) buf -= 3;
    }

    // epilogue: fp16 output
    int erow = warp_m * 48 + (lane >> 2);
    int ecol = n0 + warp_n * 32 + (lane & 3) * 2;
#pragma unroll
    for (int mt = 0; mt < 3; mt++) {
#pragma unroll
        for (int nt = 0; nt < 4; nt++) {
            int rr = row0 + erow + mt * 16;
            int cc = ecol + nt * 8;
            if (rr < N_NODES)
                *(__half2*)&g_Y[(size_t)rr * 512 + cc] =
                    __floats2half2_rn(acc[mt][nt][0], acc[mt][nt][1]);
            if (rr + 8 < N_NODES)
                *(__half2*)&g_Y[(size_t)(rr + 8) * 512 + cc] =
                    __floats2half2_rn(acc[mt][nt][2], acc[mt][nt][3]);
        }
    }
}

// ---------------- 128-wide propagation on fp16 arrays (fp32 accumulate, MLP 8) ----------------
__device__ __forceinline__ void h4_to_f4(const __half* p, float* f) {
    uint2 u = *(const uint2*)p;
    __half2 h0 = *(__half2*)&u.x;
    __half2 h1 = *(__half2*)&u.y;
    float2 a = __half22float2(h0), b = __half22float2(h1);
    f[0] = a.x; f[1] = a.y; f[2] = b.x; f[3] = b.y;
}

__device__ __forceinline__ void prop128_body(const __half* __restrict__ in,
                                             int inStride, int inOfs,
                                             float* acc, int gw, int c) {
    int beg = g_rowptr[gw], end = g_rowptr[gw + 1];
    int j = beg;
    for (; j + 8 <= end; j += 8) {
        int   s[8];
        float w[8];
        float v[8][4];
#pragma unroll
        for (int q = 0; q < 8; q++) { s[q] = g_srcs[j + q]; w[q] = g_ws[j + q]; }
#pragma unroll
        for (int q = 0; q < 8; q++)
            h4_to_f4(in + (size_t)s[q] * inStride + inOfs + c, v[q]);
#pragma unroll
        for (int q = 0; q < 8; q++) {
            acc[0] += w[q] * v[q][0]; acc[1] += w[q] * v[q][1];
            acc[2] += w[q] * v[q][2]; acc[3] += w[q] * v[q][3];
        }
    }
    for (; j < end; j++) {
        int s = g_srcs[j];
        float w = g_ws[j];
        float v[4];
        h4_to_f4(in + (size_t)s * inStride + inOfs + c, v);
#pragma unroll
        for (int q = 0; q < 4; q++) acc[q] += w * v[q];
    }
}

__global__ void k_prop128(const __half* __restrict__ in, int inStride, int inOfs,
                          const __half* __restrict__ add, int addStride, int addOfs,
                          __half* __restrict__ out) {
    int gw = (blockIdx.x * blockDim.x + threadIdx.x) >> 5;
    int lane = threadIdx.x & 31;
    if (gw >= N_NODES) return;
    int c = lane * 4;
    float acc[4];
    h4_to_f4(add + (size_t)gw * addStride + addOfs + c, acc);
    prop128_body(in, inStride, inOfs, acc, gw, c);
    uint2 o;
    *(__half2*)&o.x = __floats2half2_rn(acc[0], acc[1]);
    *(__half2*)&o.y = __floats2half2_rn(acc[2], acc[3]);
    *(uint2*)&out[(size_t)gw * HID + c] = o;
}

__global__ void k_prop128_final(const __half* __restrict__ in, int inStride, int inOfs,
                                const __half* __restrict__ add, int addStride, int addOfs,
                                const float* __restrict__ b1, const float* __restrict__ gamma,
                                const float* __restrict__ beta, const float* __restrict__ mean,
                                const float* __restrict__ var) {
    int gw = (blockIdx.x * blockDim.x + threadIdx.x) >> 5;
    int lane = threadIdx.x & 31;
    if (gw >= N_NODES) return;
    int c = lane * 4;
    float acc[4];
    h4_to_f4(add + (size_t)gw * addStride + addOfs + c, acc);
    prop128_body(in, inStride, inOfs, acc, gw, c);
    float4 bb = *(const float4*)&b1[c];
    float4 gg = *(const float4*)&gamma[c];
    float4 be = *(const float4*)&beta[c];
    float4 mm = *(const float4*)&mean[c];
    float4 vv = *(const float4*)&var[c];
    float4 r;
    r.x = fmaxf((acc[0] + bb.x - mm.x) * rsqrtf(vv.x + BN_EPS) * gg.x + be.x, 0.f);
    r.y = fmaxf((acc[1] + bb.y - mm.y) * rsqrtf(vv.y + BN_EPS) * gg.y + be.y, 0.f);
    r.z = fmaxf((acc[2] + bb.z - mm.z) * rsqrtf(vv.z + BN_EPS) * gg.z + be.z, 0.f);
    r.w = fmaxf((acc[3] + bb.w - mm.w) * rsqrtf(vv.w + BN_EPS) * gg.w + be.w, 0.f);
    *(float4*)&g_h[(size_t)gw * HID + c] = r;
}

// ---------------- GEMM2 (Ws rows padded to 16 floats; LDS.128 reads) ----------------
__global__ __launch_bounds__(256) void k_gemm2(const float* __restrict__ W2) {
    __shared__ float Ws[128 * 64];   // [f][cg*16 + c], c<15 valid, c=15 pad
    int row0 = blockIdx.x * 64;
    int tid = threadIdx.x;
    for (int idx = tid; idx < 128 * 64; idx += 256) {
        int f = idx >> 6, j = idx & 63;
        int k = j >> 4, cc = j & 15;
        Ws[idx] = (cc < OUTC) ? W2[(size_t)(k * HID + f) * OUTC + cc] : 0.f;
    }
    __syncthreads();
    int r = tid >> 2, cg = tid & 3;
    int n = row0 + r;
    float acc[16];
#pragma unroll
    for (int c = 0; c < 16; c++) acc[c] = 0.f;
    if (n < N_NODES) {
        const float* hp = g_h + (size_t)n * HID;
#pragma unroll 4
        for (int f = 0; f < 128; f++) {
            float a = __ldg(hp + f);
            const float4* wrow = (const float4*)&Ws[f * 64 + cg * 16];
#pragma unroll
            for (int q = 0; q < 4; q++) {
                float4 wv = wrow[q];
                acc[q * 4 + 0] += a * wv.x;
                acc[q * 4 + 1] += a * wv.y;
                acc[q * 4 + 2] += a * wv.z;
                acc[q * 4 + 3] += a * wv.w;
            }
        }
        float* zp = g_Z + (size_t)n * 64 + cg * 16;
#pragma unroll
        for (int q = 0; q < 4; q++)
            *(float4*)(zp + q * 4) = make_float4(acc[q * 4], acc[q * 4 + 1],
                                                 acc[q * 4 + 2], acc[q * 4 + 3]);
    }
}

// ---------------- 16-wide propagation (2 nodes per warp, unrolled x8) ----------------
__device__ __forceinline__ float prop16_body(const float* __restrict__ in,
                                             int inStride, int inOfs,
                                             float acc, int gw, int lane) {
    int beg = g_rowptr[gw], end = g_rowptr[gw + 1];
    int j = beg;
    for (; j + 8 <= end; j += 8) {
        int   s[8];
        float w[8], v[8];
#pragma unroll
        for (int q = 0; q < 8; q++) { s[q] = g_srcs[j + q]; w[q] = g_ws[j + q]; }
#pragma unroll
        for (int q = 0; q < 8; q++)
            v[q] = in[(size_t)s[q] * inStride + inOfs + lane];
#pragma unroll
        for (int q = 0; q < 8; q++) acc += w[q] * v[q];
    }
    for (; j < end; j++)
        acc += g_ws[j] * in[(size_t)g_srcs[j] * inStride + inOfs + lane];
    return acc;
}

__global__ void k_prop16(const float* __restrict__ in, int inStride, int inOfs,
                         const float* __restrict__ add, int addStride, int addOfs,
                         float* __restrict__ out) {
    int gw = (blockIdx.x * blockDim.x + threadIdx.x) >> 5;
    int lane = threadIdx.x & 31;
    int node = gw * 2 + (lane >> 4);
    int l = lane & 15;
    if (node >= N_NODES) return;
    float acc = add[(size_t)node * addStride + addOfs + l];
    acc = prop16_body(in, inStride, inOfs, acc, node, l);
    out[(size_t)node * 16 + l] = acc;
}

__global__ void k_prop16_final(const float* __restrict__ in, int inStride, int inOfs,
                               const float* __restrict__ add, int addStride, int addOfs,
                               const float* __restrict__ b2, float* __restrict__ out15) {
    int gw = (blockIdx.x * blockDim.x + threadIdx.x) >> 5;
    int lane = threadIdx.x & 31;
    int node = gw * 2 + (lane >> 4);
    int l = lane & 15;
    if (node >= N_NODES || l >= 15) return;
    float acc = add[(size_t)node * addStride + addOfs + l];
    acc = prop16_body(in, inStride, inOfs, acc, node, l);
    out15[(size_t)node * OUTC + l] = acc + b2[l];
}

// ---------------- launch ----------------
extern "C" void kernel_launch(void* const* d_in, const int* in_sizes, int n_in,
                              void* d_out, int out_size) {
    const float* x     = (const float*)d_in[0];
    const int*   esrc  = (const int*)d_in[1];
    const int*   edst  = (const int*)d_in[2];
    const float* ew    = (const float*)d_in[3];
    const float* W1    = (const float*)d_in[4];
    const float* b1    = (const float*)d_in[5];
    const float* gamma = (const float*)d_in[6];
    const float* beta  = (const float*)d_in[7];
    const float* mmean = (const float*)d_in[8];
    const float* mvar  = (const float*)d_in[9];
    const float* W2    = (const float*)d_in[10];
    const float* b2    = (const float*)d_in[11];
    float* out = (float*)d_out;

    __half *pY, *pt0, *pt1;
    float *pZ, *pu0, *pu1;
    cudaGetSymbolAddress((void**)&pY,  g_Y);
    cudaGetSymbolAddress((void**)&pt0, g_t0);
    cudaGetSymbolAddress((void**)&pt1, g_t1);
    cudaGetSymbolAddress((void**)&pZ,  g_Z);
    cudaGetSymbolAddress((void**)&pu0, g_u0);
    cudaGetSymbolAddress((void**)&pu1, g_u1);

    cudaFuncSetAttribute(k_gemm1_mma, cudaFuncAttributeMaxDynamicSharedMemorySize, SMEM_G1);

    // R11-proven topology: fork ONLY the CSR build onto a second stream at t=0
    // (overlaps split_x + split_w + gemm1); split_w stays on the main stream.
    cudaStream_t s2;
    cudaEvent_t evFork, evJoin;
    cudaStreamCreateWithFlags(&s2, cudaStreamNonBlocking);
    cudaEventCreateWithFlags(&evFork, cudaEventDisableTiming);
    cudaEventCreateWithFlags(&evJoin, cudaEventDisableTiming);

    cudaEventRecord(evFork, 0);
    cudaStreamWaitEvent(s2, evFork, 0);
    k_zero<<<(N_NODES + 255) / 256, 256, 0, s2>>>();
    k_hist<<<(N_EDGES + 255) / 256, 256, 0, s2>>>(edst);
    k_scan<<<1, 1024, 0, s2>>>();
    k_scatter<<<(N_EDGES + 255) / 256, 256, 0, s2>>>(esrc, edst, ew);
    cudaEventRecord(evJoin, s2);

    // Main stream: splits + tensor-core GEMM1 (overlapped with CSR build).
    k_split_x<<<(N_NODES * 512 + 255) / 256, 256>>>(x);
    k_split_w<<<(512 * KPAD + 255) / 256, 256>>>(W1);
    dim3 g1(4, (N_NODES + MTILE - 1) / MTILE);
    k_gemm1_mma<<<g1, 512, SMEM_G1>>>();

    // Join: props need both Y (main) and CSR (s2).
    cudaStreamWaitEvent(0, evJoin, 0);

    int pb = (N_NODES * 32 + 255) / 256;
    int pb2 = (N_NODES * 16 + 255) / 256;
    k_prop128<<<pb, 256>>>(pY, 512, 384, pY, 512, 256, pt0);   // t0 = y2 + A*y3
    k_prop128<<<pb, 256>>>(pt0, 128, 0,  pY, 512, 128, pt1);   // t1 = y1 + A*t0
    k_prop128_final<<<pb, 256>>>(pt1, 128, 0, pY, 512, 0,      // h = BNReLU(y0 + A*t1 + b1)
                                 b1, gamma, beta, mmean, mvar);

    k_gemm2<<<(N_NODES + 63) / 64, 256>>>(W2);
    k_prop16<<<pb2, 256>>>(pZ, 64, 48, pZ, 64, 32, pu0);
    k_prop16<<<pb2, 256>>>(pu0, 16, 0, pZ, 64, 16, pu1);
    k_prop16_final<<<pb2, 256>>>(pu1, 16, 0, pZ, 64, 0, b2, out);
}

// round 15
// speedup vs baseline: 1.0992x; 1.0702x over previous
#include <cuda_runtime.h>
#include <cuda_fp16.h>
#include <math.h>
#include <stdint.h>

#define N_NODES 20000
#define N_FEAT  2000
#define N_EDGES 640000
#define HID     128
#define OUTC    15
#define BN_EPS  1e-3f
#define KPAD    2048

// ---------------- scratch (device globals; no allocation allowed) ----------------
__device__ __half g_Ah[(size_t)N_NODES * KPAD];
__device__ __half g_Bh[(size_t)512 * KPAD];
__device__ __half g_Y [N_NODES * 512];   // fp16: x @ [W1_0|W1_1|W1_2|W1_3]
__device__ __half g_t0[N_NODES * HID];   // fp16 Horner temps
__device__ __half g_t1[N_NODES * HID];
__device__ float g_h [N_NODES * HID];    // fp32 post BN+ReLU (GEMM2 input)
__device__ float g_Z [N_NODES * 64];
__device__ float g_u0[N_NODES * 16];
__device__ float g_u1[N_NODES * 16];
__device__ int   g_counts[N_NODES];
__device__ int   g_rowptr[N_NODES + 1];
__device__ int   g_rowofs[N_NODES];
__device__ int   g_srcs[N_EDGES];
__device__ float g_ws [N_EDGES];

// ---------------- helpers ----------------
__device__ __forceinline__ uint32_t smem_u32(const void* p) {
    uint32_t a;
    asm("{ .reg .u64 t; cvta.to.shared.u64 t, %1; cvt.u32.u64 %0, t; }" : "=r"(a) : "l"(p));
    return a;
}
__device__ __forceinline__ void cp_async16(uint32_t dst, const void* src) {
    asm volatile("cp.async.cg.shared.global [%0], [%1], 16;" :: "r"(dst), "l"(src));
}
__device__ __forceinline__ void ldsm4(uint32_t* r, uint32_t addr) {
    asm volatile("ldmatrix.sync.aligned.m8n8.x4.shared.b16 {%0,%1,%2,%3}, [%4];"
                 : "=r"(r[0]), "=r"(r[1]), "=r"(r[2]), "=r"(r[3]) : "r"(addr));
}
__device__ __forceinline__ void mma16816h(float* d, const uint32_t* a, const uint32_t* b) {
    asm volatile(
        "mma.sync.aligned.m16n8k16.row.col.f32.f16.f16.f32 "
        "{%0,%1,%2,%3}, {%4,%5,%6,%7}, {%8,%9}, {%0,%1,%2,%3};"
        : "+f"(d[0]), "+f"(d[1]), "+f"(d[2]), "+f"(d[3])
        : "r"(a[0]), "r"(a[1]), "r"(a[2]), "r"(a[3]), "r"(b[0]), "r"(b[1]));
}

// ---------------- CSR build ----------------
__global__ void k_zero() {
    int i = blockIdx.x * blockDim.x + threadIdx.x;
    if (i < N_NODES) { g_counts[i] = 0; g_rowofs[i] = 0; }
}
__global__ void k_hist(const int* __restrict__ dst) {
    int e = blockIdx.x * blockDim.x + threadIdx.x;
    if (e < N_EDGES) atomicAdd(&g_counts[dst[e]], 1);
}
__global__ void k_scan() {
    __shared__ int sh[1024];
    __shared__ int carry;
    if (threadIdx.x == 0) carry = 0;
    __syncthreads();
    for (int base = 0; base < N_NODES; base += 1024) {
        int i = base + threadIdx.x;
        int v = (i < N_NODES) ? g_counts[i] : 0;
        sh[threadIdx.x] = v;
        __syncthreads();
        for (int off = 1; off < 1024; off <<= 1) {
            int t = (threadIdx.x >= off) ? sh[threadIdx.x - off] : 0;
            __syncthreads();
            sh[threadIdx.x] += t;
            __syncthreads();
        }
        int incl = sh[threadIdx.x] + carry;
        if (i < N_NODES) g_rowptr[i + 1] = incl;
        __syncthreads();
        if (threadIdx.x == 1023) carry = incl;
        __syncthreads();
    }
    if (threadIdx.x == 0) g_rowptr[0] = 0;
}
__global__ void k_scatter(const int* __restrict__ src, const int* __restrict__ dst,
                          const float* __restrict__ w) {
    int e = blockIdx.x * blockDim.x + threadIdx.x;
    if (e < N_EDGES) {
        int d = dst[e];
        int pos = g_rowptr[d] + atomicAdd(&g_rowofs[d], 1);
        g_srcs[pos] = src[e];
        g_ws[pos]   = w[e];
    }
}

// ---------------- split conversions ----------------
// x -> fp16, 8 elements per thread (2x float4 -> one 16B store)
__global__ void k_split_x(const float* __restrict__ x) {
    int idx = blockIdx.x * blockDim.x + threadIdx.x;
    if (idx >= N_NODES * 256) return;
    int r = idx >> 8, c8 = (idx & 255) * 8;
    uint4 o;
    if (c8 < N_FEAT) {   // N_FEAT divisible by 8 => full vector or full pad
        const float4* xp = (const float4*)&x[(size_t)r * N_FEAT + c8];
        float4 v0 = xp[0], v1 = xp[1];
        *(__half2*)&o.x = __floats2half2_rn(v0.x, v0.y);
        *(__half2*)&o.y = __floats2half2_rn(v0.z, v0.w);
        *(__half2*)&o.z = __floats2half2_rn(v1.x, v1.y);
        *(__half2*)&o.w = __floats2half2_rn(v1.z, v1.w);
    } else {
        o.x = 0u; o.y = 0u; o.z = 0u; o.w = 0u;
    }
    *(uint4*)&g_Ah[(size_t)r * KPAD + c8] = o;
}
// Bh[n][k] = fp16(W1[(n>>7)*2000 + k, n&127]);  W1 is [8000,128] row-major
__global__ void k_split_w(const float* __restrict__ W1) {
    int idx = blockIdx.x * blockDim.x + threadIdx.x;
    if (idx >= 512 * KPAD) return;
    int n = idx >> 11, k = idx & (KPAD - 1);
    float v = (k < N_FEAT) ? W1[(size_t)((n >> 7) * N_FEAT + k) * HID + (n & 127)] : 0.f;
    g_Bh[idx] = __float2half_rn(v);
}

// ---------------- GEMM1 via mma.sync (HMMA fp16, fp32 accum — proven config) ----------------
// Y = fp16(x) @ fp16(W), fp32 accum, fp16 output.
// CTA tile 192x128, 512 threads, 16 warps (4x4), warp tile 48x32, k-chunk 64.
// 3-stage cp.async ring, ONE __syncthreads per chunk. 144B rows => conflict-free ldmatrix.
#define RS      144                 // 128 data + 16 pad
#define ATILEB  (192 * RS)          // 27648
#define BTILEB  (128 * RS)          // 18432
#define STGB    (ATILEB + BTILEB)   // 46080
#define NCH     32                  // 2048 / 64
#define SMEM_G1 (3 * STGB)          // 138240
#define MTILE   192

__global__ __launch_bounds__(512, 1) void k_gemm1_mma() {
    extern __shared__ __align__(16) char smem[];
    uint32_t sb = smem_u32(smem);
    int tid = threadIdx.x;
    int lane = tid & 31, wid = tid >> 5;
    int warp_m = wid & 3, warp_n = wid >> 2;
    int n0   = blockIdx.x * 128;    // 0..3  N-tile (fast dim: share A tile in L2)
    int row0 = blockIdx.y * MTILE;  // 0..104

    float acc[3][4][4];
#pragma unroll
    for (int mt = 0; mt < 3; mt++)
#pragma unroll
        for (int nt = 0; nt < 4; nt++)
#pragma unroll
            for (int i = 0; i < 4; i++) acc[mt][nt][i] = 0.f;

    // ldmatrix lane addressing
    int g = lane >> 3, r = lane & 7;
    uint32_t a_off = (uint32_t)((warp_m * 48 + (g & 1) * 8 + r) * RS + (g >> 1) * 16);
    uint32_t b_off = (uint32_t)((warp_n * 32 + (g >> 1) * 8 + r) * RS + (g & 1) * 16);

    // loads per chunk: A 192 rows x 8 segs + B 128 x 8 = 2560 cp16 => 5 per thread
    auto load_chunk = [&](int kc, int buf) {
        uint32_t ab = sb + buf * STGB;
        uint32_t bb = ab + ATILEB;
#pragma unroll
        for (int i = 0; i < 5; i++) {
            int idx = tid + i * 512;
            if (idx < 1536) {
                int rr = idx >> 3, seg = idx & 7;
                int grr = row0 + rr; if (grr >= N_NODES) grr = N_NODES - 1;
                cp_async16(ab + rr * RS + seg * 16,
                           g_Ah + (size_t)grr * KPAD + kc * 64 + seg * 8);
            } else {
                int j = idx - 1536;
                int rr = j >> 3, seg = j & 7;
                cp_async16(bb + rr * RS + seg * 16,
                           g_Bh + (size_t)(n0 + rr) * KPAD + kc * 64 + seg * 8);
            }
        }
        asm volatile("cp.async.commit_group;" ::: "memory");
    };

    load_chunk(0, 0);
    load_chunk(1, 1);

    int buf = 0;
    for (int c = 0; c < NCH; c++) {
        if (c + 1 < NCH) asm volatile("cp.async.wait_group 1;" ::: "memory");
        else             asm volatile("cp.async.wait_group 0;" ::: "memory");
        __syncthreads();
        uint32_t ab = sb + buf * STGB;
        uint32_t bb = ab + ATILEB;
        if (c + 2 < NCH) {
            int nbuf = buf + 2; if (nbuf >= 3) nbuf -= 3;
            load_chunk(c + 2, nbuf);
        }
#pragma unroll
        for (int ks = 0; ks < 4; ks++) {
            uint32_t afr[3][4], bfr[2][4];
#pragma unroll
            for (int mt = 0; mt < 3; mt++)
                ldsm4(afr[mt], ab + a_off + mt * 16 * RS + ks * 32);
#pragma unroll
            for (int bp = 0; bp < 2; bp++)
                ldsm4(bfr[bp], bb + b_off + bp * 16 * RS + ks * 32);
#pragma unroll
            for (int mt = 0; mt < 3; mt++)
#pragma unroll
                for (int nt = 0; nt < 4; nt++)
                    mma16816h(acc[mt][nt], afr[mt], &bfr[nt >> 1][(nt & 1) * 2]);
        }
        buf++; if (buf >= 3) buf -= 3;
    }

    // epilogue: fp16 output
    int erow = warp_m * 48 + (lane >> 2);
    int ecol = n0 + warp_n * 32 + (lane & 3) * 2;
#pragma unroll
    for (int mt = 0; mt < 3; mt++) {
#pragma unroll
        for (int nt = 0; nt < 4; nt++) {
            int rr = row0 + erow + mt * 16;
            int cc = ecol + nt * 8;
            if (rr < N_NODES)
                *(__half2*)&g_Y[(size_t)rr * 512 + cc] =
                    __floats2half2_rn(acc[mt][nt][0], acc[mt][nt][1]);
            if (rr + 8 < N_NODES)
                *(__half2*)&g_Y[(size_t)(rr + 8) * 512 + cc] =
                    __floats2half2_rn(acc[mt][nt][2], acc[mt][nt][3]);
        }
    }
}

// ---------------- 128-wide propagation on fp16 arrays (fp32 accumulate, MLP 8) ----------------
__device__ __forceinline__ void h4_to_f4(const __half* p, float* f) {
    uint2 u = *(const uint2*)p;
    __half2 h0 = *(__half2*)&u.x;
    __half2 h1 = *(__half2*)&u.y;
    float2 a = __half22float2(h0), b = __half22float2(h1);
    f[0] = a.x; f[1] = a.y; f[2] = b.x; f[3] = b.y;
}

__device__ __forceinline__ void prop128_body(const __half* __restrict__ in,
                                             int inStride, int inOfs,
                                             float* acc, int gw, int c) {
    int beg = g_rowptr[gw], end = g_rowptr[gw + 1];
    int j = beg;
    for (; j + 8 <= end; j += 8) {
        int   s[8];
        float w[8];
        float v[8][4];
#pragma unroll
        for (int q = 0; q < 8; q++) { s[q] = g_srcs[j + q]; w[q] = g_ws[j + q]; }
#pragma unroll
        for (int q = 0; q < 8; q++)
            h4_to_f4(in + (size_t)s[q] * inStride + inOfs + c, v[q]);
#pragma unroll
        for (int q = 0; q < 8; q++) {
            acc[0] += w[q] * v[q][0]; acc[1] += w[q] * v[q][1];
            acc[2] += w[q] * v[q][2]; acc[3] += w[q] * v[q][3];
        }
    }
    for (; j < end; j++) {
        int s = g_srcs[j];
        float w = g_ws[j];
        float v[4];
        h4_to_f4(in + (size_t)s * inStride + inOfs + c, v);
#pragma unroll
        for (int q = 0; q < 4; q++) acc[q] += w * v[q];
    }
}

__global__ void k_prop128(const __half* __restrict__ in, int inStride, int inOfs,
                          const __half* __restrict__ add, int addStride, int addOfs,
                          __half* __restrict__ out) {
    int gw = (blockIdx.x * blockDim.x + threadIdx.x) >> 5;
    int lane = threadIdx.x & 31;
    if (gw >= N_NODES) return;
    int c = lane * 4;
    float acc[4];
    h4_to_f4(add + (size_t)gw * addStride + addOfs + c, acc);
    prop128_body(in, inStride, inOfs, acc, gw, c);
    uint2 o;
    *(__half2*)&o.x = __floats2half2_rn(acc[0], acc[1]);
    *(__half2*)&o.y = __floats2half2_rn(acc[2], acc[3]);
    *(uint2*)&out[(size_t)gw * HID + c] = o;
}

__global__ void k_prop128_final(const __half* __restrict__ in, int inStride, int inOfs,
                                const __half* __restrict__ add, int addStride, int addOfs,
                                const float* __restrict__ b1, const float* __restrict__ gamma,
                                const float* __restrict__ beta, const float* __restrict__ mean,
                                const float* __restrict__ var) {
    int gw = (blockIdx.x * blockDim.x + threadIdx.x) >> 5;
    int lane = threadIdx.x & 31;
    if (gw >= N_NODES) return;
    int c = lane * 4;
    float acc[4];
    h4_to_f4(add + (size_t)gw * addStride + addOfs + c, acc);
    prop128_body(in, inStride, inOfs, acc, gw, c);
    float4 bb = *(const float4*)&b1[c];
    float4 gg = *(const float4*)&gamma[c];
    float4 be = *(const float4*)&beta[c];
    float4 mm = *(const float4*)&mean[c];
    float4 vv = *(const float4*)&var[c];
    float4 r;
    r.x = fmaxf((acc[0] + bb.x - mm.x) * rsqrtf(vv.x + BN_EPS) * gg.x + be.x, 0.f);
    r.y = fmaxf((acc[1] + bb.y - mm.y) * rsqrtf(vv.y + BN_EPS) * gg.y + be.y, 0.f);
    r.z = fmaxf((acc[2] + bb.z - mm.z) * rsqrtf(vv.z + BN_EPS) * gg.z + be.z, 0.f);
    r.w = fmaxf((acc[3] + bb.w - mm.w) * rsqrtf(vv.w + BN_EPS) * gg.w + be.w, 0.f);
    *(float4*)&g_h[(size_t)gw * HID + c] = r;
}

// ---------------- GEMM2 (proven 60-float-row version) ----------------
__global__ __launch_bounds__(256) void k_gemm2(const float* __restrict__ W2) {
    __shared__ float Ws[128 * 60];
    int row0 = blockIdx.x * 64;
    int tid = threadIdx.x;
    for (int idx = tid; idx < 128 * 60; idx += 256) {
        int f = idx / 60, j = idx % 60;
        int k = j / 15, cc = j % 15;
        Ws[idx] = W2[(size_t)(k * HID + f) * OUTC + cc];
    }
    __syncthreads();
    int r = tid >> 2, cg = tid & 3;
    int n = row0 + r;
    float acc[15];
#pragma unroll
    for (int c = 0; c < 15; c++) acc[c] = 0.f;
    if (n < N_NODES) {
        const float* hp = g_h + (size_t)n * HID;
#pragma unroll 4
        for (int f = 0; f < 128; f++) {
            float a = __ldg(hp + f);
            const float* wrow = &Ws[f * 60 + cg * 15];
#pragma unroll
            for (int c = 0; c < 15; c++) acc[c] += a * wrow[c];
        }
        float* zp = g_Z + (size_t)n * 64 + cg * 16;
#pragma unroll
        for (int c = 0; c < 15; c++) zp[c] = acc[c];
        zp[15] = 0.f;
    }
}

// ---------------- 16-wide propagation (2 nodes per warp, unrolled x4 — proven) ----------------
__device__ __forceinline__ float prop16_body(const float* __restrict__ in,
                                             int inStride, int inOfs,
                                             float acc, int gw, int lane) {
    int beg = g_rowptr[gw], end = g_rowptr[gw + 1];
    int j = beg;
    for (; j + 4 <= end; j += 4) {
        int s0 = g_srcs[j], s1 = g_srcs[j + 1], s2 = g_srcs[j + 2], s3 = g_srcs[j + 3];
        float w0 = g_ws[j], w1 = g_ws[j + 1], w2 = g_ws[j + 2], w3 = g_ws[j + 3];
        float v0 = in[(size_t)s0 * inStride + inOfs + lane];
        float v1 = in[(size_t)s1 * inStride + inOfs + lane];
        float v2 = in[(size_t)s2 * inStride + inOfs + lane];
        float v3 = in[(size_t)s3 * inStride + inOfs + lane];
        acc += w0 * v0 + w1 * v1 + w2 * v2 + w3 * v3;
    }
    for (; j < end; j++)
        acc += g_ws[j] * in[(size_t)g_srcs[j] * inStride + inOfs + lane];
    return acc;
}

__global__ void k_prop16(const float* __restrict__ in, int inStride, int inOfs,
                         const float* __restrict__ add, int addStride, int addOfs,
                         float* __restrict__ out) {
    int gw = (blockIdx.x * blockDim.x + threadIdx.x) >> 5;
    int lane = threadIdx.x & 31;
    int node = gw * 2 + (lane >> 4);
    int l = lane & 15;
    if (node >= N_NODES) return;
    float acc = add[(size_t)node * addStride + addOfs + l];
    acc = prop16_body(in, inStride, inOfs, acc, node, l);
    out[(size_t)node * 16 + l] = acc;
}

__global__ void k_prop16_final(const float* __restrict__ in, int inStride, int inOfs,
                               const float* __restrict__ add, int addStride, int addOfs,
                               const float* __restrict__ b2, float* __restrict__ out15) {
    int gw = (blockIdx.x * blockDim.x + threadIdx.x) >> 5;
    int lane = threadIdx.x & 31;
    int node = gw * 2 + (lane >> 4);
    int l = lane & 15;
    if (node >= N_NODES || l >= 15) return;
    float acc = add[(size_t)node * addStride + addOfs + l];
    acc = prop16_body(in, inStride, inOfs, acc, node, l);
    out15[(size_t)node * OUTC + l] = acc + b2[l];
}

// ---------------- launch ----------------
extern "C" void kernel_launch(void* const* d_in, const int* in_sizes, int n_in,
                              void* d_out, int out_size) {
    const float* x     = (const float*)d_in[0];
    const int*   esrc  = (const int*)d_in[1];
    const int*   edst  = (const int*)d_in[2];
    const float* ew    = (const float*)d_in[3];
    const float* W1    = (const float*)d_in[4];
    const float* b1    = (const float*)d_in[5];
    const float* gamma = (const float*)d_in[6];
    const float* beta  = (const float*)d_in[7];
    const float* mmean = (const float*)d_in[8];
    const float* mvar  = (const float*)d_in[9];
    const float* W2    = (const float*)d_in[10];
    const float* b2    = (const float*)d_in[11];
    float* out = (float*)d_out;

    __half *pY, *pt0, *pt1;
    float *pZ, *pu0, *pu1;
    cudaGetSymbolAddress((void**)&pY,  g_Y);
    cudaGetSymbolAddress((void**)&pt0, g_t0);
    cudaGetSymbolAddress((void**)&pt1, g_t1);
    cudaGetSymbolAddress((void**)&pZ,  g_Z);
    cudaGetSymbolAddress((void**)&pu0, g_u0);
    cudaGetSymbolAddress((void**)&pu1, g_u1);

    cudaFuncSetAttribute(k_gemm1_mma, cudaFuncAttributeMaxDynamicSharedMemorySize, SMEM_G1);

    // R11-proven topology: fork ONLY the CSR build onto a second stream at t=0
    // (overlaps split_x + split_w + gemm1); split_w stays on the main stream.
    cudaStream_t s2;
    cudaEvent_t evFork, evJoin;
    cudaStreamCreateWithFlags(&s2, cudaStreamNonBlocking);
    cudaEventCreateWithFlags(&evFork, cudaEventDisableTiming);
    cudaEventCreateWithFlags(&evJoin, cudaEventDisableTiming);

    cudaEventRecord(evFork, 0);
    cudaStreamWaitEvent(s2, evFork, 0);
    k_zero<<<(N_NODES + 255) / 256, 256, 0, s2>>>();
    k_hist<<<(N_EDGES + 255) / 256, 256, 0, s2>>>(edst);
    k_scan<<<1, 1024, 0, s2>>>();
    k_scatter<<<(N_EDGES + 255) / 256, 256, 0, s2>>>(esrc, edst, ew);
    cudaEventRecord(evJoin, s2);

    // Main stream: splits + tensor-core GEMM1 (overlapped with CSR build).
    k_split_x<<<(N_NODES * 256 + 255) / 256, 256>>>(x);
    k_split_w<<<(512 * KPAD + 255) / 256, 256>>>(W1);
    dim3 g1(4, (N_NODES + MTILE - 1) / MTILE);
    k_gemm1_mma<<<g1, 512, SMEM_G1>>>();

    // Join: props need both Y (main) and CSR (s2).
    cudaStreamWaitEvent(0, evJoin, 0);

    int pb = (N_NODES * 32 + 255) / 256;
    int pb2 = (N_NODES * 16 + 255) / 256;
    k_prop128<<<pb, 256>>>(pY, 512, 384, pY, 512, 256, pt0);   // t0 = y2 + A*y3
    k_prop128<<<pb, 256>>>(pt0, 128, 0,  pY, 512, 128, pt1);   // t1 = y1 + A*t0
    k_prop128_final<<<pb, 256>>>(pt1, 128, 0, pY, 512, 0,      // h = BNReLU(y0 + A*t1 + b1)
                                 b1, gamma, beta, mmean, mvar);

    k_gemm2<<<(N_NODES + 63) / 64, 256>>>(W2);
    k_prop16<<<pb2, 256>>>(pZ, 64, 48, pZ, 64, 32, pu0);
    k_prop16<<<pb2, 256>>>(pu0, 16, 0, pZ, 64, 16, pu1);
    k_prop16_final<<<pb2, 256>>>(pu1, 16, 0, pZ, 64, 0, b2, out);
}